// round 5
// baseline (speedup 1.0000x reference)
#include <cuda_runtime.h>
#include <cuda_fp16.h>
#include <math.h>

#define NB   32
#define NL   2048
#define ND   512
#define NDFF 256
#define NBLK 6
#define FEPS 1e-6f
#define LCHUNK 64
#define NCHUNK (NL / LCHUNK)   // 32

// ---------------- device scratch (no allocations allowed) ----------------
__device__ float  g_q[NB * ND];               // evolving query
__device__ float  g_scores[NB * NL];          // raw scores
__device__ float  g_s_all[NBLK][NB * NL];     // softmax probs per block
__device__ float  g_Apart[NB * NCHUNK * ND];  // partial attention outputs
__device__ __half g_kh[(size_t)NB * NL * ND]; // fp16 K (64MB)
__device__ __half g_vh[(size_t)NB * NL * ND]; // fp16 V (64MB)

// ---------------- helpers ----------------
__device__ __forceinline__ float block_sum_512(float v, float* red) {
    #pragma unroll
    for (int o = 16; o; o >>= 1) v += __shfl_xor_sync(0xffffffffu, v, o);
    int w = threadIdx.x >> 5;
    if ((threadIdx.x & 31) == 0) red[w] = v;
    __syncthreads();
    if (threadIdx.x < 16) {
        float t = red[threadIdx.x];
        #pragma unroll
        for (int o = 8; o; o >>= 1) t += __shfl_xor_sync(0xffffu, t, o);
        if (threadIdx.x == 0) red[0] = t;
    }
    __syncthreads();
    float r = red[0];
    __syncthreads();
    return r;
}

// dot of 8 fp16 (packed in uint4) with 8 fp32 (two float4), accumulated fp32
__device__ __forceinline__ float hdot8(uint4 kv, float4 q0, float4 q1) {
    float2 f0 = __half22float2(*reinterpret_cast<__half2*>(&kv.x));
    float2 f1 = __half22float2(*reinterpret_cast<__half2*>(&kv.y));
    float2 f2 = __half22float2(*reinterpret_cast<__half2*>(&kv.z));
    float2 f3 = __half22float2(*reinterpret_cast<__half2*>(&kv.w));
    float a = 0.f, b = 0.f;
    a = fmaf(f0.x, q0.x, a); b = fmaf(f0.y, q0.y, b);
    a = fmaf(f1.x, q0.z, a); b = fmaf(f1.y, q0.w, b);
    a = fmaf(f2.x, q1.x, a); b = fmaf(f2.y, q1.y, b);
    a = fmaf(f3.x, q1.z, a); b = fmaf(f3.y, q1.w, b);
    return a + b;
}

__device__ __forceinline__ void hfma8(uint4 x, float s, float* a) {
    float2 f0 = __half22float2(*reinterpret_cast<__half2*>(&x.x));
    float2 f1 = __half22float2(*reinterpret_cast<__half2*>(&x.y));
    float2 f2 = __half22float2(*reinterpret_cast<__half2*>(&x.z));
    float2 f3 = __half22float2(*reinterpret_cast<__half2*>(&x.w));
    a[0] = fmaf(s, f0.x, a[0]); a[1] = fmaf(s, f0.y, a[1]);
    a[2] = fmaf(s, f1.x, a[2]); a[3] = fmaf(s, f1.y, a[3]);
    a[4] = fmaf(s, f2.x, a[4]); a[5] = fmaf(s, f2.y, a[5]);
    a[6] = fmaf(s, f3.x, a[6]); a[7] = fmaf(s, f3.y, a[7]);
}

// ---------------- kernels ----------------
__global__ void initq_kernel(const float* __restrict__ q) {
    int i = blockIdx.x * blockDim.x + threadIdx.x;
    if (i < NB * ND) g_q[i] = q[i];
}

// one-time fp32 -> fp16 conversion of K and V; thread handles 8 floats
__global__ void convert_kernel(const float* __restrict__ k, const float* __restrict__ v) {
    const size_t NTOT = (size_t)NB * NL * ND;     // per array
    size_t i = (size_t)blockIdx.x * blockDim.x + threadIdx.x;
    const float4* src;
    __half* dst;
    size_t off;
    if (i < NTOT / 8) { src = (const float4*)k; dst = g_kh; off = i; }
    else              { src = (const float4*)v; dst = g_vh; off = i - NTOT / 8; }
    float4 a = __ldcs(src + off * 2);
    float4 b = __ldcs(src + off * 2 + 1);
    uint4 out;
    *reinterpret_cast<__half2*>(&out.x) = __floats2half2_rn(a.x, a.y);
    *reinterpret_cast<__half2*>(&out.y) = __floats2half2_rn(a.z, a.w);
    *reinterpret_cast<__half2*>(&out.z) = __floats2half2_rn(b.x, b.y);
    *reinterpret_cast<__half2*>(&out.w) = __floats2half2_rn(b.z, b.w);
    reinterpret_cast<uint4*>(dst)[off] = out;
}

// scores[b,l] = <q[b,:], kh[b,l,:]> / sqrt(D); one warp per (b,l)
__global__ void scores_kernel() {
    int warp = (blockIdx.x * blockDim.x + threadIdx.x) >> 5;
    int lane = threadIdx.x & 31;
    if (warp >= NB * NL) return;
    int b = warp >> 11;          // / 2048
    const uint4*  k4 = reinterpret_cast<const uint4*>(g_kh + (size_t)warp * ND); // 64 uint4/row
    const float4* q4 = reinterpret_cast<const float4*>(g_q + b * ND);            // 128 float4/row

    uint4 kv0 = __ldcs(k4 + lane);
    uint4 kv1 = __ldcs(k4 + lane + 32);
    float4 qa0 = q4[lane * 2];
    float4 qa1 = q4[lane * 2 + 1];
    float4 qb0 = q4[64 + lane * 2];
    float4 qb1 = q4[64 + lane * 2 + 1];

    float acc = hdot8(kv0, qa0, qa1) + hdot8(kv1, qb0, qb1);

    #pragma unroll
    for (int o = 16; o; o >>= 1) acc += __shfl_xor_sync(0xffffffffu, acc, o);
    if (lane == 0) g_scores[warp] = acc * 0.04419417382415922f;  // 1/sqrt(512)
}

// softmax over L per batch; writes contiguous g_s_all[blk]
__global__ void softmax_kernel(int blk) {
    int b = blockIdx.x;
    int t = threadIdx.x;            // 512 threads
    __shared__ float red[16];
    const float* sc = g_scores + b * NL;

    float e[NL / 512];
    float m = -INFINITY;
    #pragma unroll
    for (int i = 0; i < NL / 512; i++) {
        e[i] = sc[t + i * 512];
        m = fmaxf(m, e[i]);
    }
    #pragma unroll
    for (int o = 16; o; o >>= 1) m = fmaxf(m, __shfl_xor_sync(0xffffffffu, m, o));
    int w = t >> 5;
    if ((t & 31) == 0) red[w] = m;
    __syncthreads();
    if (t < 16) {
        float x = red[t];
        #pragma unroll
        for (int o = 8; o; o >>= 1) x = fmaxf(x, __shfl_xor_sync(0xffffu, x, o));
        if (t == 0) red[0] = x;
    }
    __syncthreads();
    m = red[0];
    __syncthreads();

    float sum = 0.f;
    #pragma unroll
    for (int i = 0; i < NL / 512; i++) {
        e[i] = expf(e[i] - m);
        sum += e[i];
    }
    float tot = block_sum_512(sum, red);
    float inv = 1.0f / tot;

    #pragma unroll
    for (int i = 0; i < NL / 512; i++) {
        int l = t + i * 512;
        g_s_all[blk][b * NL + l] = e[i] * inv;
    }
}

// partial A over fp16 V: one block per (l-chunk, b); 128 threads.
// Threads split into 2 row-groups of 64; each thread owns 8 output dims;
// two groups process even/odd rows of each 2-row pair, combined via smem.
__global__ void apart_kernel(int blk) {
    int c = blockIdx.x;     // 0..NCHUNK-1
    int b = blockIdx.y;     // 0..31
    int t = threadIdx.x;    // 0..127
    int half = t >> 6;      // 0 or 1
    int col  = t & 63;      // owns dims [col*8, col*8+8)

    __shared__ float ss[LCHUNK];
    __shared__ float part[ND];     // group-1 partials

    if (t < LCHUNK) ss[t] = g_s_all[blk][b * NL + c * LCHUNK + t];
    __syncthreads();

    // base: rows of this chunk; row = 512 halves = 64 uint4; 2-row pair = 128 uint4
    const uint4* vp = reinterpret_cast<const uint4*>(
        g_vh + ((size_t)b * NL + (size_t)c * LCHUNK) * ND) + half * 64 + col;

    float a[8] = {0, 0, 0, 0, 0, 0, 0, 0};
    #pragma unroll 4
    for (int g = 0; g < LCHUNK / 2; g++) {
        uint4 x = __ldcs(vp + g * 128);
        hfma8(x, ss[2 * g + half], a);
    }

    if (half == 1) {
        float4* p4 = reinterpret_cast<float4*>(part);
        p4[col * 2]     = make_float4(a[0], a[1], a[2], a[3]);
        p4[col * 2 + 1] = make_float4(a[4], a[5], a[6], a[7]);
    }
    __syncthreads();
    if (half == 0) {
        float4* o4 = reinterpret_cast<float4*>(g_Apart + (b * NCHUNK + c) * ND);
        const float4* p4 = reinterpret_cast<const float4*>(part);
        float4 p0 = p4[col * 2], p1 = p4[col * 2 + 1];
        o4[col * 2]     = make_float4(a[0] + p0.x, a[1] + p0.y, a[2] + p0.z, a[3] + p0.w);
        o4[col * 2 + 1] = make_float4(a[4] + p1.x, a[5] + p1.y, a[6] + p1.z, a[7] + p1.w);
    }
}

// fused tail: reduce partials + residual + Norm1 + FF(relu) + FF2 + residual + Norm2
__global__ void tail_kernel(const float* __restrict__ W1, const float* __restrict__ b1,
                            const float* __restrict__ W2, const float* __restrict__ b2,
                            const float* __restrict__ al1, const float* __restrict__ bi1,
                            const float* __restrict__ al2, const float* __restrict__ bi2,
                            float* __restrict__ out, int blk, int write_out, int out_off) {
    int b = blockIdx.x;   // 32
    int d = threadIdx.x;  // 512
    __shared__ float red[16];
    __shared__ float sh_q[ND];
    __shared__ float sh_p[ND];     // FF1 partials (2 halves)
    __shared__ float sh_h[NDFF];

    // 1. A = sum partials, x = A + q
    float x = g_q[b * ND + d];
    #pragma unroll 8
    for (int c = 0; c < NCHUNK; c++) x += g_Apart[(b * NCHUNK + c) * ND + d];

    // 2. Norm1 (ddof=1, denom std+eps)
    float mu  = block_sum_512(x, red) * (1.0f / ND);
    float dev = x - mu;
    float var = block_sum_512(dev * dev, red) * (1.0f / (ND - 1));
    float qn1 = al1[blk * ND + d] * dev / (sqrtf(var) + FEPS) + bi1[blk * ND + d];
    sh_q[d] = qn1;
    __syncthreads();

    // 3. FF1: h = relu(q_ @ W1 + b1). 512 threads = (half, j); MLP 8.
    {
        int j    = d & (NDFF - 1);
        int half = d >> 8;
        const float* w  = W1 + (size_t)blk * ND * NDFF + (size_t)(half * 256) * NDFF + j;
        const float* xq = sh_q + half * 256;
        float c0 = 0.f, c1 = 0.f, c2 = 0.f, c3 = 0.f;
        float c4 = 0.f, c5 = 0.f, c6 = 0.f, c7 = 0.f;
        #pragma unroll 4
        for (int i = 0; i < 256; i += 8) {
            c0 = fmaf(xq[i + 0], __ldg(w + (i + 0) * NDFF), c0);
            c1 = fmaf(xq[i + 1], __ldg(w + (i + 1) * NDFF), c1);
            c2 = fmaf(xq[i + 2], __ldg(w + (i + 2) * NDFF), c2);
            c3 = fmaf(xq[i + 3], __ldg(w + (i + 3) * NDFF), c3);
            c4 = fmaf(xq[i + 4], __ldg(w + (i + 4) * NDFF), c4);
            c5 = fmaf(xq[i + 5], __ldg(w + (i + 5) * NDFF), c5);
            c6 = fmaf(xq[i + 6], __ldg(w + (i + 6) * NDFF), c6);
            c7 = fmaf(xq[i + 7], __ldg(w + (i + 7) * NDFF), c7);
        }
        sh_p[d] = ((c0 + c1) + (c2 + c3)) + ((c4 + c5) + (c6 + c7));
    }
    __syncthreads();
    if (d < NDFF) {
        float hv = sh_p[d] + sh_p[d + 256] + b1[blk * NDFF + d];
        sh_h[d] = fmaxf(hv, 0.f);
    }
    __syncthreads();

    // 4. FF2: ff = h @ W2 + b2 (512 threads, one output d each, MLP 8)
    float acc = b2[blk * ND + d];
    {
        const float* w2 = W2 + (size_t)blk * NDFF * ND + d;  // col d, stride ND
        float c0 = 0.f, c1 = 0.f, c2 = 0.f, c3 = 0.f;
        float c4 = 0.f, c5 = 0.f, c6 = 0.f, c7 = 0.f;
        #pragma unroll 4
        for (int j = 0; j < NDFF; j += 8) {
            c0 = fmaf(sh_h[j + 0], __ldg(w2 + (j + 0) * ND), c0);
            c1 = fmaf(sh_h[j + 1], __ldg(w2 + (j + 1) * ND), c1);
            c2 = fmaf(sh_h[j + 2], __ldg(w2 + (j + 2) * ND), c2);
            c3 = fmaf(sh_h[j + 3], __ldg(w2 + (j + 3) * ND), c3);
            c4 = fmaf(sh_h[j + 4], __ldg(w2 + (j + 4) * ND), c4);
            c5 = fmaf(sh_h[j + 5], __ldg(w2 + (j + 5) * ND), c5);
            c6 = fmaf(sh_h[j + 6], __ldg(w2 + (j + 6) * ND), c6);
            c7 = fmaf(sh_h[j + 7], __ldg(w2 + (j + 7) * ND), c7);
        }
        acc += ((c0 + c1) + (c2 + c3)) + ((c4 + c5) + (c6 + c7));
    }
    float x2 = qn1 + acc;

    // 5. Norm2
    float mu2  = block_sum_512(x2, red) * (1.0f / ND);
    float dev2 = x2 - mu2;
    float var2 = block_sum_512(dev2 * dev2, red) * (1.0f / (ND - 1));
    float qn2 = al2[blk * ND + d] * dev2 / (sqrtf(var2) + FEPS) + bi2[blk * ND + d];

    g_q[b * ND + d] = qn2;
    if (write_out) out[b * (2 * ND) + out_off + d] = qn2;
}

// final: assemble weights (B, L, NBLK) from per-block contiguous buffers
__global__ void combine_kernel(float* __restrict__ wout) {
    int i = blockIdx.x * blockDim.x + threadIdx.x;  // (b*NL + l)
    if (i >= NB * NL) return;
    float vals[NBLK];
    #pragma unroll
    for (int blk = 0; blk < NBLK; blk++) vals[blk] = g_s_all[blk][i];
    float* o = wout + (size_t)i * NBLK;
    #pragma unroll
    for (int blk = 0; blk < NBLK; blk++) o[blk] = vals[blk];
}

// ---------------- launch ----------------
extern "C" void kernel_launch(void* const* d_in, const int* in_sizes, int n_in,
                              void* d_out, int out_size) {
    const float* q   = (const float*)d_in[0];
    const float* k   = (const float*)d_in[1];
    const float* v   = (const float*)d_in[2];
    const float* W1  = (const float*)d_in[3];
    const float* b1  = (const float*)d_in[4];
    const float* W2  = (const float*)d_in[5];
    const float* b2  = (const float*)d_in[6];
    const float* al1 = (const float*)d_in[7];
    const float* bi1 = (const float*)d_in[8];
    const float* al2 = (const float*)d_in[9];
    const float* bi2 = (const float*)d_in[10];

    float* out_p = (float*)d_out;                 // (32, 1024)
    float* w_p   = (float*)d_out + NB * 2 * ND;   // (32, 2048, 6)

    initq_kernel<<<(NB * ND + 255) / 256, 256>>>(q);
    // convert K and V to fp16: 2 arrays * 33.5M floats / 8 per thread
    {
        size_t nthreads = 2 * ((size_t)NB * NL * ND) / 8;
        convert_kernel<<<(unsigned)(nthreads / 256), 256>>>(k, v);
    }

    for (int blk = 0; blk < NBLK; blk++) {
        scores_kernel<<<(NB * NL * 32) / 256, 256>>>();
        softmax_kernel<<<NB, 512>>>(blk);
        apart_kernel<<<dim3(NCHUNK, NB), 128>>>(blk);
        int wr = (blk == 2 || blk == 5) ? 1 : 0;
        int off = (blk == 5) ? ND : 0;
        tail_kernel<<<NB, ND>>>(W1, b1, W2, b2, al1, bi1, al2, bi2,
                                out_p, blk, wr, off);
    }
    combine_kernel<<<(NB * NL + 255) / 256, 256>>>(w_p);
}

// round 6
// speedup vs baseline: 1.1412x; 1.1412x over previous
#include <cuda_runtime.h>
#include <cuda_fp16.h>
#include <math.h>

#define NB   32
#define NL   2048
#define ND   512
#define NDFF 256
#define NBLK 6
#define FEPS 1e-6f
#define LCHUNK 64
#define NCHUNK (NL / LCHUNK)   // 32

// ---------------- device scratch (no allocations allowed) ----------------
__device__ float  g_q[NB * ND];               // evolving query
__device__ float  g_scores[NB * NL];          // raw scores
__device__ float  g_s_all[NBLK][NB * NL];     // softmax probs per block
__device__ float  g_Apart[NB * NCHUNK * ND];  // partial attention outputs
__device__ __half g_kh[(size_t)NB * NL * ND]; // fp16 K (64MB)
__device__ __half g_vh[(size_t)NB * NL * ND]; // fp16 V (64MB)

// ---------------- helpers ----------------
__device__ __forceinline__ float block_sum_512(float v, float* red) {
    #pragma unroll
    for (int o = 16; o; o >>= 1) v += __shfl_xor_sync(0xffffffffu, v, o);
    int w = threadIdx.x >> 5;
    if ((threadIdx.x & 31) == 0) red[w] = v;
    __syncthreads();
    if (threadIdx.x < 16) {
        float t = red[threadIdx.x];
        #pragma unroll
        for (int o = 8; o; o >>= 1) t += __shfl_xor_sync(0xffffu, t, o);
        if (threadIdx.x == 0) red[0] = t;
    }
    __syncthreads();
    float r = red[0];
    __syncthreads();
    return r;
}

// dot of 8 fp16 (uint4) with 8 fp32 (two float4)
__device__ __forceinline__ float hdot8(uint4 kv, float4 q0, float4 q1) {
    float2 f0 = __half22float2(*reinterpret_cast<__half2*>(&kv.x));
    float2 f1 = __half22float2(*reinterpret_cast<__half2*>(&kv.y));
    float2 f2 = __half22float2(*reinterpret_cast<__half2*>(&kv.z));
    float2 f3 = __half22float2(*reinterpret_cast<__half2*>(&kv.w));
    float a = 0.f, b = 0.f;
    a = fmaf(f0.x, q0.x, a); b = fmaf(f0.y, q0.y, b);
    a = fmaf(f1.x, q0.z, a); b = fmaf(f1.y, q0.w, b);
    a = fmaf(f2.x, q1.x, a); b = fmaf(f2.y, q1.y, b);
    a = fmaf(f3.x, q1.z, a); b = fmaf(f3.y, q1.w, b);
    return a + b;
}

__device__ __forceinline__ void hfma8(uint4 x, float s, float* a) {
    float2 f0 = __half22float2(*reinterpret_cast<__half2*>(&x.x));
    float2 f1 = __half22float2(*reinterpret_cast<__half2*>(&x.y));
    float2 f2 = __half22float2(*reinterpret_cast<__half2*>(&x.z));
    float2 f3 = __half22float2(*reinterpret_cast<__half2*>(&x.w));
    a[0] = fmaf(s, f0.x, a[0]); a[1] = fmaf(s, f0.y, a[1]);
    a[2] = fmaf(s, f1.x, a[2]); a[3] = fmaf(s, f1.y, a[3]);
    a[4] = fmaf(s, f2.x, a[4]); a[5] = fmaf(s, f2.y, a[5]);
    a[6] = fmaf(s, f3.x, a[6]); a[7] = fmaf(s, f3.y, a[7]);
}

__device__ __forceinline__ uint2 pack_h4(float4 a) {
    uint2 r;
    *reinterpret_cast<__half2*>(&r.x) = __floats2half2_rn(a.x, a.y);
    *reinterpret_cast<__half2*>(&r.y) = __floats2half2_rn(a.z, a.w);
    return r;
}

// ---------------- kernels ----------------
__global__ void initq_kernel(const float* __restrict__ q) {
    int i = blockIdx.x * blockDim.x + threadIdx.x;
    if (i < NB * ND) g_q[i] = q[i];
}

// block 0 scores: fp32 K -> scores, and emit fp16 K. one warp per (b,l).
__global__ void scores0_kernel(const float* __restrict__ k) {
    int warp = (blockIdx.x * blockDim.x + threadIdx.x) >> 5;
    int lane = threadIdx.x & 31;
    if (warp >= NB * NL) return;
    int b = warp >> 11;
    const float4* k4 = reinterpret_cast<const float4*>(k + (size_t)warp * ND) + lane;
    const float4* q4 = reinterpret_cast<const float4*>(g_q + b * ND) + lane;

    float4 kv0 = __ldcs(k4 + 0);
    float4 kv1 = __ldcs(k4 + 32);
    float4 kv2 = __ldcs(k4 + 64);
    float4 kv3 = __ldcs(k4 + 96);
    float4 qv0 = q4[0], qv1 = q4[32], qv2 = q4[64], qv3 = q4[96];

    // emit fp16 K: row viewed as uint2[128], same indices as float4
    uint2* kh2 = reinterpret_cast<uint2*>(g_kh + (size_t)warp * ND);
    kh2[lane + 0]  = pack_h4(kv0);
    kh2[lane + 32] = pack_h4(kv1);
    kh2[lane + 64] = pack_h4(kv2);
    kh2[lane + 96] = pack_h4(kv3);

    float a = 0.f, bb = 0.f;
    a = fmaf(kv0.x, qv0.x, a); bb = fmaf(kv0.y, qv0.y, bb);
    a = fmaf(kv0.z, qv0.z, a); bb = fmaf(kv0.w, qv0.w, bb);
    a = fmaf(kv1.x, qv1.x, a); bb = fmaf(kv1.y, qv1.y, bb);
    a = fmaf(kv1.z, qv1.z, a); bb = fmaf(kv1.w, qv1.w, bb);
    a = fmaf(kv2.x, qv2.x, a); bb = fmaf(kv2.y, qv2.y, bb);
    a = fmaf(kv2.z, qv2.z, a); bb = fmaf(kv2.w, qv2.w, bb);
    a = fmaf(kv3.x, qv3.x, a); bb = fmaf(kv3.y, qv3.y, bb);
    a = fmaf(kv3.z, qv3.z, a); bb = fmaf(kv3.w, qv3.w, bb);
    float acc = a + bb;

    #pragma unroll
    for (int o = 16; o; o >>= 1) acc += __shfl_xor_sync(0xffffffffu, acc, o);
    if (lane == 0) g_scores[warp] = acc * 0.04419417382415922f;
}

// blocks 1..5 scores: fp16 K, TWO rows per warp (4 x 16B loads in flight)
__global__ void scoresH_kernel() {
    int warp = (blockIdx.x * blockDim.x + threadIdx.x) >> 5;  // 0..NB*NL/2-1
    int lane = threadIdx.x & 31;
    int row0 = warp * 2;
    int row1 = row0 + 1;
    int b = row0 >> 11;
    const uint4* kA = reinterpret_cast<const uint4*>(g_kh + (size_t)row0 * ND);
    const uint4* kB = reinterpret_cast<const uint4*>(g_kh + (size_t)row1 * ND);
    const float4* q4 = reinterpret_cast<const float4*>(g_q + b * ND);

    uint4 a0 = __ldcs(kA + lane);
    uint4 a1 = __ldcs(kA + lane + 32);
    uint4 b0 = __ldcs(kB + lane);
    uint4 b1 = __ldcs(kB + lane + 32);
    float4 q0 = q4[lane * 2], q1 = q4[lane * 2 + 1];
    float4 q2 = q4[64 + lane * 2], q3 = q4[64 + lane * 2 + 1];

    float accA = hdot8(a0, q0, q1) + hdot8(a1, q2, q3);
    float accB = hdot8(b0, q0, q1) + hdot8(b1, q2, q3);

    #pragma unroll
    for (int o = 16; o; o >>= 1) {
        accA += __shfl_xor_sync(0xffffffffu, accA, o);
        accB += __shfl_xor_sync(0xffffffffu, accB, o);
    }
    if (lane == 0) {
        g_scores[row0] = accA * 0.04419417382415922f;
        g_scores[row1] = accB * 0.04419417382415922f;
    }
}

// softmax over L per batch; writes contiguous g_s_all[blk]
__global__ void softmax_kernel(int blk) {
    int b = blockIdx.x;
    int t = threadIdx.x;            // 512 threads
    __shared__ float red[16];
    const float* sc = g_scores + b * NL;

    float e[NL / 512];
    float m = -INFINITY;
    #pragma unroll
    for (int i = 0; i < NL / 512; i++) {
        e[i] = sc[t + i * 512];
        m = fmaxf(m, e[i]);
    }
    #pragma unroll
    for (int o = 16; o; o >>= 1) m = fmaxf(m, __shfl_xor_sync(0xffffffffu, m, o));
    int w = t >> 5;
    if ((t & 31) == 0) red[w] = m;
    __syncthreads();
    if (t < 16) {
        float x = red[t];
        #pragma unroll
        for (int o = 8; o; o >>= 1) x = fmaxf(x, __shfl_xor_sync(0xffffu, x, o));
        if (t == 0) red[0] = x;
    }
    __syncthreads();
    m = red[0];
    __syncthreads();

    float sum = 0.f;
    #pragma unroll
    for (int i = 0; i < NL / 512; i++) {
        e[i] = expf(e[i] - m);
        sum += e[i];
    }
    float tot = block_sum_512(sum, red);
    float inv = 1.0f / tot;

    #pragma unroll
    for (int i = 0; i < NL / 512; i++) {
        int l = t + i * 512;
        g_s_all[blk][b * NL + l] = e[i] * inv;
    }
}

// block 0 apart: fp32 V, emit fp16 V. one block per (l-chunk, b); 128 threads.
__global__ void apart0_kernel(const float* __restrict__ v) {
    int c = blockIdx.x;
    int b = blockIdx.y;
    int t = threadIdx.x;    // 0..127, owns float4 column t
    __shared__ float ss[LCHUNK];
    if (t < LCHUNK) ss[t] = g_s_all[0][b * NL + c * LCHUNK + t];
    __syncthreads();
    size_t rowbase = ((size_t)b * NL + (size_t)c * LCHUNK);
    const float4* vp = reinterpret_cast<const float4*>(v + rowbase * ND) + t;
    uint2* vh2 = reinterpret_cast<uint2*>(g_vh + rowbase * ND) + t;
    float4 a0 = {0,0,0,0}, a1 = {0,0,0,0}, a2 = {0,0,0,0}, a3 = {0,0,0,0};
    #pragma unroll 4
    for (int l = 0; l < LCHUNK; l += 4) {
        float4 v0 = __ldcs(vp + (l + 0) * 128);
        float4 v1 = __ldcs(vp + (l + 1) * 128);
        float4 v2 = __ldcs(vp + (l + 2) * 128);
        float4 v3 = __ldcs(vp + (l + 3) * 128);
        vh2[(l + 0) * 128] = pack_h4(v0);
        vh2[(l + 1) * 128] = pack_h4(v1);
        vh2[(l + 2) * 128] = pack_h4(v2);
        vh2[(l + 3) * 128] = pack_h4(v3);
        float s0 = ss[l + 0], s1 = ss[l + 1], s2 = ss[l + 2], s3 = ss[l + 3];
        a0.x = fmaf(s0, v0.x, a0.x); a0.y = fmaf(s0, v0.y, a0.y);
        a0.z = fmaf(s0, v0.z, a0.z); a0.w = fmaf(s0, v0.w, a0.w);
        a1.x = fmaf(s1, v1.x, a1.x); a1.y = fmaf(s1, v1.y, a1.y);
        a1.z = fmaf(s1, v1.z, a1.z); a1.w = fmaf(s1, v1.w, a1.w);
        a2.x = fmaf(s2, v2.x, a2.x); a2.y = fmaf(s2, v2.y, a2.y);
        a2.z = fmaf(s2, v2.z, a2.z); a2.w = fmaf(s2, v2.w, a2.w);
        a3.x = fmaf(s3, v3.x, a3.x); a3.y = fmaf(s3, v3.y, a3.y);
        a3.z = fmaf(s3, v3.z, a3.z); a3.w = fmaf(s3, v3.w, a3.w);
    }
    float4 r;
    r.x = (a0.x + a1.x) + (a2.x + a3.x);
    r.y = (a0.y + a1.y) + (a2.y + a3.y);
    r.z = (a0.z + a1.z) + (a2.z + a3.z);
    r.w = (a0.w + a1.w) + (a2.w + a3.w);
    reinterpret_cast<float4*>(g_Apart + (b * NCHUNK + c) * ND)[t] = r;
}

// blocks 1..5 apart: fp16 V; 128 threads = (half, col); 8 loads in flight
__global__ void apartH_kernel(int blk) {
    int c = blockIdx.x;
    int b = blockIdx.y;
    int t = threadIdx.x;
    int half = t >> 6;      // 0/1: even/odd row of each pair
    int col  = t & 63;      // uint4 column (8 dims)

    __shared__ float ss[LCHUNK];
    __shared__ float part[ND];
    if (t < LCHUNK) ss[t] = g_s_all[blk][b * NL + c * LCHUNK + t];
    __syncthreads();

    const uint4* vp = reinterpret_cast<const uint4*>(
        g_vh + ((size_t)b * NL + (size_t)c * LCHUNK) * ND) + half * 64 + col;

    float a[8] = {0, 0, 0, 0, 0, 0, 0, 0};
    #pragma unroll
    for (int g = 0; g < LCHUNK / 2; g += 8) {
        uint4 x0 = __ldcs(vp + (g + 0) * 128);
        uint4 x1 = __ldcs(vp + (g + 1) * 128);
        uint4 x2 = __ldcs(vp + (g + 2) * 128);
        uint4 x3 = __ldcs(vp + (g + 3) * 128);
        uint4 x4 = __ldcs(vp + (g + 4) * 128);
        uint4 x5 = __ldcs(vp + (g + 5) * 128);
        uint4 x6 = __ldcs(vp + (g + 6) * 128);
        uint4 x7 = __ldcs(vp + (g + 7) * 128);
        hfma8(x0, ss[2 * (g + 0) + half], a);
        hfma8(x1, ss[2 * (g + 1) + half], a);
        hfma8(x2, ss[2 * (g + 2) + half], a);
        hfma8(x3, ss[2 * (g + 3) + half], a);
        hfma8(x4, ss[2 * (g + 4) + half], a);
        hfma8(x5, ss[2 * (g + 5) + half], a);
        hfma8(x6, ss[2 * (g + 6) + half], a);
        hfma8(x7, ss[2 * (g + 7) + half], a);
    }

    if (half == 1) {
        float4* p4 = reinterpret_cast<float4*>(part);
        p4[col * 2]     = make_float4(a[0], a[1], a[2], a[3]);
        p4[col * 2 + 1] = make_float4(a[4], a[5], a[6], a[7]);
    }
    __syncthreads();
    if (half == 0) {
        float4* o4 = reinterpret_cast<float4*>(g_Apart + (b * NCHUNK + c) * ND);
        const float4* p4 = reinterpret_cast<const float4*>(part);
        float4 p0 = p4[col * 2], p1 = p4[col * 2 + 1];
        o4[col * 2]     = make_float4(a[0] + p0.x, a[1] + p0.y, a[2] + p0.z, a[3] + p0.w);
        o4[col * 2 + 1] = make_float4(a[4] + p1.x, a[5] + p1.y, a[6] + p1.z, a[7] + p1.w);
    }
}

// fused tail: reduce partials + residual + Norm1 + FF(relu) + FF2 + residual + Norm2
__global__ void tail_kernel(const float* __restrict__ W1, const float* __restrict__ b1,
                            const float* __restrict__ W2, const float* __restrict__ b2,
                            const float* __restrict__ al1, const float* __restrict__ bi1,
                            const float* __restrict__ al2, const float* __restrict__ bi2,
                            float* __restrict__ out, int blk, int write_out, int out_off) {
    int b = blockIdx.x;
    int d = threadIdx.x;
    __shared__ float red[16];
    __shared__ float sh_q[ND];
    __shared__ float sh_p[ND];
    __shared__ float sh_h[NDFF];

    float x = g_q[b * ND + d];
    #pragma unroll 8
    for (int c = 0; c < NCHUNK; c++) x += g_Apart[(b * NCHUNK + c) * ND + d];

    float mu  = block_sum_512(x, red) * (1.0f / ND);
    float dev = x - mu;
    float var = block_sum_512(dev * dev, red) * (1.0f / (ND - 1));
    float qn1 = al1[blk * ND + d] * dev / (sqrtf(var) + FEPS) + bi1[blk * ND + d];
    sh_q[d] = qn1;
    __syncthreads();

    {
        int j    = d & (NDFF - 1);
        int half = d >> 8;
        const float* w  = W1 + (size_t)blk * ND * NDFF + (size_t)(half * 256) * NDFF + j;
        const float* xq = sh_q + half * 256;
        float c0 = 0.f, c1 = 0.f, c2 = 0.f, c3 = 0.f;
        float c4 = 0.f, c5 = 0.f, c6 = 0.f, c7 = 0.f;
        #pragma unroll 4
        for (int i = 0; i < 256; i += 8) {
            c0 = fmaf(xq[i + 0], __ldg(w + (i + 0) * NDFF), c0);
            c1 = fmaf(xq[i + 1], __ldg(w + (i + 1) * NDFF), c1);
            c2 = fmaf(xq[i + 2], __ldg(w + (i + 2) * NDFF), c2);
            c3 = fmaf(xq[i + 3], __ldg(w + (i + 3) * NDFF), c3);
            c4 = fmaf(xq[i + 4], __ldg(w + (i + 4) * NDFF), c4);
            c5 = fmaf(xq[i + 5], __ldg(w + (i + 5) * NDFF), c5);
            c6 = fmaf(xq[i + 6], __ldg(w + (i + 6) * NDFF), c6);
            c7 = fmaf(xq[i + 7], __ldg(w + (i + 7) * NDFF), c7);
        }
        sh_p[d] = ((c0 + c1) + (c2 + c3)) + ((c4 + c5) + (c6 + c7));
    }
    __syncthreads();
    if (d < NDFF) {
        float hv = sh_p[d] + sh_p[d + 256] + b1[blk * NDFF + d];
        sh_h[d] = fmaxf(hv, 0.f);
    }
    __syncthreads();

    float acc = b2[blk * ND + d];
    {
        const float* w2 = W2 + (size_t)blk * NDFF * ND + d;
        float c0 = 0.f, c1 = 0.f, c2 = 0.f, c3 = 0.f;
        float c4 = 0.f, c5 = 0.f, c6 = 0.f, c7 = 0.f;
        #pragma unroll 4
        for (int j = 0; j < NDFF; j += 8) {
            c0 = fmaf(sh_h[j + 0], __ldg(w2 + (j + 0) * ND), c0);
            c1 = fmaf(sh_h[j + 1], __ldg(w2 + (j + 1) * ND), c1);
            c2 = fmaf(sh_h[j + 2], __ldg(w2 + (j + 2) * ND), c2);
            c3 = fmaf(sh_h[j + 3], __ldg(w2 + (j + 3) * ND), c3);
            c4 = fmaf(sh_h[j + 4], __ldg(w2 + (j + 4) * ND), c4);
            c5 = fmaf(sh_h[j + 5], __ldg(w2 + (j + 5) * ND), c5);
            c6 = fmaf(sh_h[j + 6], __ldg(w2 + (j + 6) * ND), c6);
            c7 = fmaf(sh_h[j + 7], __ldg(w2 + (j + 7) * ND), c7);
        }
        acc += ((c0 + c1) + (c2 + c3)) + ((c4 + c5) + (c6 + c7));
    }
    float x2 = qn1 + acc;

    float mu2  = block_sum_512(x2, red) * (1.0f / ND);
    float dev2 = x2 - mu2;
    float var2 = block_sum_512(dev2 * dev2, red) * (1.0f / (ND - 1));
    float qn2 = al2[blk * ND + d] * dev2 / (sqrtf(var2) + FEPS) + bi2[blk * ND + d];

    g_q[b * ND + d] = qn2;
    if (write_out) out[b * (2 * ND) + out_off + d] = qn2;
}

// final: assemble weights (B, L, NBLK)
__global__ void combine_kernel(float* __restrict__ wout) {
    int i = blockIdx.x * blockDim.x + threadIdx.x;
    if (i >= NB * NL) return;
    float vals[NBLK];
    #pragma unroll
    for (int blk = 0; blk < NBLK; blk++) vals[blk] = g_s_all[blk][i];
    float* o = wout + (size_t)i * NBLK;
    #pragma unroll
    for (int blk = 0; blk < NBLK; blk++) o[blk] = vals[blk];
}

// ---------------- launch ----------------
extern "C" void kernel_launch(void* const* d_in, const int* in_sizes, int n_in,
                              void* d_out, int out_size) {
    const float* q   = (const float*)d_in[0];
    const float* k   = (const float*)d_in[1];
    const float* v   = (const float*)d_in[2];
    const float* W1  = (const float*)d_in[3];
    const float* b1  = (const float*)d_in[4];
    const float* W2  = (const float*)d_in[5];
    const float* b2  = (const float*)d_in[6];
    const float* al1 = (const float*)d_in[7];
    const float* bi1 = (const float*)d_in[8];
    const float* al2 = (const float*)d_in[9];
    const float* bi2 = (const float*)d_in[10];

    float* out_p = (float*)d_out;                 // (32, 1024)
    float* w_p   = (float*)d_out + NB * 2 * ND;   // (32, 2048, 6)

    initq_kernel<<<(NB * ND + 255) / 256, 256>>>(q);

    for (int blk = 0; blk < NBLK; blk++) {
        if (blk == 0)
            scores0_kernel<<<(NB * NL * 32) / 256, 256>>>(k);
        else
            scoresH_kernel<<<(NB * NL / 2 * 32) / 256, 256>>>();
        softmax_kernel<<<NB, 512>>>(blk);
        if (blk == 0)
            apart0_kernel<<<dim3(NCHUNK, NB), 128>>>(v);
        else
            apartH_kernel<<<dim3(NCHUNK, NB), 128>>>(blk);
        int wr = (blk == 2 || blk == 5) ? 1 : 0;
        int off = (blk == 5) ? ND : 0;
        tail_kernel<<<NB, ND>>>(W1, b1, W2, b2, al1, bi1, al2, bi2,
                                out_p, blk, wr, off);
    }
    combine_kernel<<<(NB * NL + 255) / 256, 256>>>(w_p);
}